// round 13
// baseline (speedup 1.0000x reference)
#include <cuda_runtime.h>
#include <cuda_fp16.h>
#include <math.h>
#include <cstdint>

#define BATCH 4096
#define UNITS 1024
#define OUT_STEPS 200
#define SEQ_LEN 5
#define TOTAL_STEPS 204        // 5 warmup + 199 decode
#define NTILES 1024            // 32 mt x 32 nt
#define NCTA 296               // 2 CTAs/SM x 148 SMs (must all be co-resident)

#define BK 64
#define NSTG 16                // K = 1024 fp16
#define BM 128
#define BN 128
#define NTHREADS 256

#define A_STG 16384                     // 128 rows x 128B
#define STG_BYTES (2 * 16384)           // A + B
#define NBUF 3
#define SMEM_GEMM (NBUF * STG_BYTES)    // 96KB
#define SMEM_TOTAL (SMEM_GEMM + 128 * 4 + 256 * 4)   // + predv[128] + pp[256]

// ---------------- device globals ----------------
__device__ __half g_A[2][BATCH * 1024];   // ping-pong hidden state, fp16
__device__ __half g_B[4096 * 1024];       // permuted R (fp16), row C, K-major
__device__ float g_c[BATCH * UNITS];
__device__ float g_predpart[2][BATCH * 32];  // per-(row, nt) partial h.w1, parity by step
__device__ int   g_cnt[32];               // per-mt completion counters (monotonic)
__device__ float g_kwP[4096];
__device__ float g_biasP[4096];

// ---------------- helpers ----------------
__device__ __forceinline__ uint32_t smem_u32(const void* p) {
    uint32_t a;
    asm("{ .reg .u64 t; cvta.to.shared.u64 t, %1; cvt.u32.u64 %0, t; }" : "=r"(a) : "l"(p));
    return a;
}
__device__ __forceinline__ void cp16(uint32_t saddr, const void* gaddr) {
    asm volatile("cp.async.cg.shared.global [%0], [%1], 16;" :: "r"(saddr), "l"(gaddr));
}
__device__ __forceinline__ void cp_commit() {
    asm volatile("cp.async.commit_group;" ::: "memory");
}
template<int N> __device__ __forceinline__ void cp_wait() {
    asm volatile("cp.async.wait_group %0;" :: "n"(N) : "memory");
}
__device__ __forceinline__ void ldsm4(uint32_t* r, uint32_t addr) {
    asm volatile("ldmatrix.sync.aligned.m8n8.x4.shared.b16 {%0,%1,%2,%3}, [%4];"
                 : "=r"(r[0]), "=r"(r[1]), "=r"(r[2]), "=r"(r[3]) : "r"(addr));
}
__device__ __forceinline__ void mma16816(float* c, const uint32_t* a, const uint32_t* b) {
    asm volatile(
        "mma.sync.aligned.m16n8k16.row.col.f32.f16.f16.f32 "
        "{%0,%1,%2,%3}, {%4,%5,%6,%7}, {%8,%9}, {%0,%1,%2,%3};"
        : "+f"(c[0]), "+f"(c[1]), "+f"(c[2]), "+f"(c[3])
        : "r"(a[0]), "r"(a[1]), "r"(a[2]), "r"(a[3]), "r"(b[0]), "r"(b[1]));
}
__device__ __forceinline__ float sigm(float x) { return 1.0f / (1.0f + __expf(-x)); }
__device__ __forceinline__ float tanh_fast(float x) {
    float t = __expf(-2.0f * fabsf(x));
    float r = (1.0f - t) / (1.0f + t);
    return copysignf(r, x);
}

// ---------------- prep: build permuted fp16 B ----------------
// Permuted column C <- (unit u, gate g):
//   C = (u>>4)*64 + (g>>1)*32 + (u&3)*8 + ((u>>2)&3)*2 + (g&1)
// Inverse: u = (C>>6)*16 + ((C>>1)&3)*4 + ((C>>3)&3) ; g = ((C>>5)&1)*2 + (C&1)
__global__ void prep_kernel(const float* __restrict__ R, const float* __restrict__ Kw,
                            const float* __restrict__ bias) {
    int idx = blockIdx.x * blockDim.x + threadIdx.x;   // np*1024 + k
    if (idx >= 4096 * 1024) return;
    int np = idx >> 10;
    int k  = idx & 1023;
    int u = ((np >> 6) << 4) | (((np >> 1) & 3) << 2) | ((np >> 3) & 3);
    int g = (((np >> 5) & 1) << 1) | (np & 1);
    int n = g * 1024 + u;
    float v = R[k * 4096 + n];
    g_B[np * 1024 + k] = __float2half_rn(v);
    if (k == 0) { g_kwP[np] = Kw[n]; g_biasP[np] = bias[n]; }
}

__global__ void zero_kernel() {
    int i = blockIdx.x * blockDim.x + threadIdx.x;
    if (i < BATCH * UNITS) {
        g_c[i] = 0.0f;
        if (i < BATCH * 512) ((uint32_t*)g_A[0])[i] = 0;   // 2M halfs
        if (i < 32) g_cnt[i] = 0;
    }
}

// ---------------- persistent fused LSTM (GEMM + gates + pred head) ----------------
__global__ void __launch_bounds__(NTHREADS, 2) lstm_persist(
    const float* __restrict__ inputs, const float* __restrict__ w1,
    const float* __restrict__ b1p, const float* __restrict__ w2p,
    const float* __restrict__ b2p, float* __restrict__ out)
{
    extern __shared__ char smem[];
    const uint32_t sb = smem_u32(smem);
    float* predv = reinterpret_cast<float*>(smem + SMEM_GEMM);   // [128]
    float* pp    = predv + 128;                                  // [256] (2 slots/row)

    const int tid  = threadIdx.x;
    const int wid  = tid >> 5;
    const int lane = tid & 31;
    const int wm   = wid >> 1;       // 0..3
    const int wn   = wid & 1;        // 0..1
    const int krot = wid & 3;
    const int cprow = tid >> 3;
    const int cpch  = tid & 7;
    const int a_r  = lane & 15;
    const int a_cb = lane >> 4;
    const int b_rr = (lane & 7) + ((lane >> 4) << 3);
    const int b_cb = (lane >> 3) & 1;
    const int q  = lane & 3;
    const int tr = lane >> 2;
    const float b1v = b1p[0], w2v = w2p[0], b2v = b2p[0];

    for (int gid = blockIdx.x; gid < TOTAL_STEPS * NTILES; gid += NCTA) {
        const int s    = gid >> 10;
        const int tile = gid & (NTILES - 1);
        const int mt   = tile >> 5;
        const int nt   = tile & 31;
        const int m0   = mt * BM;
        const int n0p  = nt * BN;
        const int pin  = s & 1;
        const __half* __restrict__ Ain = g_A[pin];
        __half* __restrict__ Aout = g_A[pin ^ 1];

        // -------- dependency wait: all (mt,*) tiles of step s-1 done --------
        if (s > 0) {
            if (tid == 0) {
                while (((volatile int*)g_cnt)[mt] < 32 * s) __nanosleep(128);
            }
            __syncthreads();
        }

        // -------- prepass: finalize pred for these 128 rows; zero pp --------
        if (tid < 128) {
            pp[tid * 2] = 0.0f; pp[tid * 2 + 1] = 0.0f;
            if (s >= 5) {
                const float* pr = &g_predpart[(s - 1) & 1][(m0 + tid) * 32];
                float sum = 0.0f;
                #pragma unroll
                for (int j4 = 0; j4 < 8; j4++) {
                    float4 v = *reinterpret_cast<const float4*>(&pr[j4 * 4]);
                    sum += (v.x + v.y) + (v.z + v.w);
                }
                float x = fmaxf(sum + b1v, 0.0f);
                float p = (s == 5) ? x : fmaf(x, w2v, b2v);
                predv[tid] = p;
                if (nt == 0) out[(m0 + tid) * OUT_STEPS + (s - 5)] = p;
            }
        }
        // (ordered before epilogue reads by the 16 stage barriers below)

        // -------- GEMM --------
        float acc[2][8][4];
        #pragma unroll
        for (int a = 0; a < 2; a++)
            #pragma unroll
            for (int b = 0; b < 8; b++)
                #pragma unroll
                for (int c = 0; c < 4; c++) acc[a][b][c] = 0.0f;

        auto issue = [&](int st) {
            const int buf = st % NBUF;
            const int kk0 = st * BK;
            const uint32_t ab = sb + buf * STG_BYTES;
            const uint32_t bb = ab + A_STG;
            #pragma unroll
            for (int p = 0; p < 4; p++) {
                int row = cprow + p * 32;
                uint32_t so = row * 128 + ((cpch ^ (row & 7)) << 4);
                cp16(ab + so, &Ain[(m0 + row) * 1024 + kk0 + cpch * 8]);
            }
            #pragma unroll
            for (int p = 0; p < 4; p++) {
                int row = cprow + p * 32;
                uint32_t so = row * 128 + ((cpch ^ (row & 7)) << 4);
                cp16(bb + so, &g_B[(uint64_t)(n0p + row) * 1024 + kk0 + cpch * 8]);
            }
            cp_commit();
        };

        issue(0);
        issue(1);

        #pragma unroll 1
        for (int st = 0; st < NSTG; st++) {
            if (st == NSTG - 1) cp_wait<0>();
            else                cp_wait<1>();
            __syncthreads();
            if (st + 2 < NSTG) issue(st + 2);

            const uint32_t ab = sb + (st % NBUF) * STG_BYTES;
            const uint32_t bb = ab + A_STG;

            #pragma unroll
            for (int kk = 0; kk < 4; kk++) {
                const int kq = (kk + krot) & 3;
                uint32_t af[2][4], bf[4][4];
                {
                    int ch = kq * 2 + a_cb;
                    #pragma unroll
                    for (int mi = 0; mi < 2; mi++) {
                        int row = wm * 32 + mi * 16 + a_r;
                        ldsm4(af[mi], ab + row * 128 + ((ch ^ (row & 7)) << 4));
                    }
                }
                {
                    int ch = kq * 2 + b_cb;
                    #pragma unroll
                    for (int jp = 0; jp < 4; jp++) {
                        int row = wn * 64 + jp * 16 + b_rr;
                        ldsm4(bf[jp], bb + row * 128 + ((ch ^ (row & 7)) << 4));
                    }
                }
                #pragma unroll
                for (int mi = 0; mi < 2; mi++)
                    #pragma unroll
                    for (int j = 0; j < 8; j++)
                        mma16816(acc[mi][j], af[mi], &bf[j >> 1][(j & 1) * 2]);
            }
        }

        // -------- epilogue: gates, c/h update, pred partials --------
        float kwv[8][2], bsv[8][2];
        #pragma unroll
        for (int j = 0; j < 8; j++) {
            int C = n0p + wn * 64 + 8 * j + 2 * q;
            float2 kw2 = *reinterpret_cast<const float2*>(&g_kwP[C]);
            float2 bs2 = *reinterpret_cast<const float2*>(&g_biasP[C]);
            kwv[j][0] = kw2.x; kwv[j][1] = kw2.y;
            bsv[j][0] = bs2.x; bsv[j][1] = bs2.y;
        }
        const int u0 = (nt * 2 + wn) * 16 + 4 * q;   // 4 consecutive units
        const float4 w1v = *reinterpret_cast<const float4*>(&w1[u0]);

        #pragma unroll
        for (int mi = 0; mi < 2; mi++) {
            #pragma unroll
            for (int h = 0; h < 2; h++) {
                const int rl  = wm * 32 + mi * 16 + tr + 8 * h;   // local row
                const int row = m0 + rl;
                float xb = (s < SEQ_LEN) ? inputs[row * SEQ_LEN + s] : predv[rl];
                float4 cold = *reinterpret_cast<const float4*>(&g_c[row * 1024 + u0]);
                float co[4] = {cold.x, cold.y, cold.z, cold.w};
                float cn[4], hf[4];
                __half hh4[4];
                #pragma unroll
                for (int jl = 0; jl < 4; jl++) {
                    float zi = acc[mi][jl    ][2 * h    ] + xb * kwv[jl    ][0] + bsv[jl    ][0];
                    float zf = acc[mi][jl    ][2 * h + 1] + xb * kwv[jl    ][1] + bsv[jl    ][1];
                    float zg = acc[mi][jl + 4][2 * h    ] + xb * kwv[jl + 4][0] + bsv[jl + 4][0];
                    float zo = acc[mi][jl + 4][2 * h + 1] + xb * kwv[jl + 4][1] + bsv[jl + 4][1];
                    float ig = sigm(zi);
                    float fg = sigm(zf);
                    float gg = tanh_fast(zg);
                    float og = sigm(zo);
                    float cc = fg * co[jl] + ig * gg;
                    cn[jl] = cc;
                    float hh = og * tanh_fast(cc);
                    hf[jl] = hh;
                    hh4[jl] = __float2half_rn(hh);
                }
                float4 cv = {cn[0], cn[1], cn[2], cn[3]};
                *reinterpret_cast<float4*>(&g_c[row * 1024 + u0]) = cv;
                uint2 hv;
                memcpy(&hv, hh4, 8);
                *reinterpret_cast<uint2*>(&Aout[row * 1024 + u0]) = hv;
                // pred partial: deterministic quad reduce (q=0..3 share a row)
                float part = hf[0] * w1v.x + hf[1] * w1v.y + hf[2] * w1v.z + hf[3] * w1v.w;
                part += __shfl_xor_sync(0xffffffffu, part, 1);
                part += __shfl_xor_sync(0xffffffffu, part, 2);
                if (q == 0) pp[rl * 2 + wn] = part;
            }
        }

        __syncthreads();   // pp visible
        if (tid < 128)
            g_predpart[s & 1][(m0 + tid) * 32 + nt] = pp[tid * 2] + pp[tid * 2 + 1];
        __threadfence();   // every thread fences its own global stores (c, h, predpart)
        __syncthreads();
        if (tid == 0) atomicAdd(&g_cnt[mt], 1);
    }

    // -------- final prediction column out[199] (from h after last step) --------
    if (blockIdx.x < 32) {
        const int mt = blockIdx.x;
        if (tid == 0) {
            while (((volatile int*)g_cnt)[mt] < 32 * TOTAL_STEPS) __nanosleep(128);
        }
        __syncthreads();
        if (tid < 128) {
            const float* pr = &g_predpart[(TOTAL_STEPS - 1) & 1][(mt * BM + tid) * 32];
            float sum = 0.0f;
            #pragma unroll
            for (int j4 = 0; j4 < 8; j4++) {
                float4 v = *reinterpret_cast<const float4*>(&pr[j4 * 4]);
                sum += (v.x + v.y) + (v.z + v.w);
            }
            float x = fmaxf(sum + b1v, 0.0f);
            out[(mt * BM + tid) * OUT_STEPS + 199] = fmaf(x, w2v, b2v);
        }
    }
}

extern "C" void kernel_launch(void* const* d_in, const int* in_sizes, int n_in,
                              void* d_out, int out_size)
{
    const float* inputs = (const float*)d_in[0];
    const float* Kw     = (const float*)d_in[1];
    const float* R      = (const float*)d_in[2];
    const float* bias   = (const float*)d_in[3];
    const float* w1     = (const float*)d_in[4];
    const float* b1     = (const float*)d_in[5];
    const float* w2     = (const float*)d_in[6];
    const float* b2     = (const float*)d_in[7];
    float* out = (float*)d_out;

    cudaFuncSetAttribute(lstm_persist, cudaFuncAttributeMaxDynamicSharedMemorySize, SMEM_TOTAL);

    zero_kernel<<<(BATCH * UNITS + 255) / 256, 256>>>();
    prep_kernel<<<(4096 * 1024 + 255) / 256, 256>>>(R, Kw, bias);
    lstm_persist<<<NCTA, NTHREADS, SMEM_TOTAL>>>(inputs, w1, b1, w2, b2, out);
}

// round 14
// speedup vs baseline: 1.1267x; 1.1267x over previous
#include <cuda_runtime.h>
#include <cuda_fp16.h>
#include <math.h>
#include <cstdint>

#define BATCH 4096
#define UNITS 1024
#define OUT_STEPS 200
#define SEQ_LEN 5
#define TOTAL_STEPS 204

#define BK 64
#define NSTG 16          // K=1024, plain fp16 R
#define BM 128
#define BN 128           // permuted z columns (= 32 units x 4 gates)
#define NTHREADS 256

#define A_STG 16384                     // 128 rows x 128B (k64 fp16)
#define STG_BYTES (2 * 16384)           // A + B = 32KB
#define NBUF 3
#define SMEM_GEMM (NBUF * STG_BYTES)    // 96KB
#define SMEM_TOTAL (SMEM_GEMM + 128 * 4 + 256 * 4)   // + predv[128] + pp[256]

// ---------------- device globals ----------------
__device__ __half g_A[2][BATCH * 1024];   // ping-pong hidden state, fp16
__device__ __half g_B[4096 * 1024];       // permuted R (fp16), row C, K-major
__device__ float g_c[BATCH * UNITS];
__device__ float g_predpart[2][BATCH * 32];  // per-(row,nt) partial h.w1, parity by step
__device__ float g_kwP[4096];
__device__ float g_biasP[4096];

// ---------------- helpers ----------------
__device__ __forceinline__ uint32_t smem_u32(const void* p) {
    uint32_t a;
    asm("{ .reg .u64 t; cvta.to.shared.u64 t, %1; cvt.u32.u64 %0, t; }" : "=r"(a) : "l"(p));
    return a;
}
__device__ __forceinline__ void cp16(uint32_t saddr, const void* gaddr) {
    asm volatile("cp.async.cg.shared.global [%0], [%1], 16;" :: "r"(saddr), "l"(gaddr));
}
__device__ __forceinline__ void cp_commit() {
    asm volatile("cp.async.commit_group;" ::: "memory");
}
template<int N> __device__ __forceinline__ void cp_wait() {
    asm volatile("cp.async.wait_group %0;" :: "n"(N) : "memory");
}
__device__ __forceinline__ void ldsm4(uint32_t* r, uint32_t addr) {
    asm volatile("ldmatrix.sync.aligned.m8n8.x4.shared.b16 {%0,%1,%2,%3}, [%4];"
                 : "=r"(r[0]), "=r"(r[1]), "=r"(r[2]), "=r"(r[3]) : "r"(addr));
}
__device__ __forceinline__ void mma16816(float* c, const uint32_t* a, const uint32_t* b) {
    asm volatile(
        "mma.sync.aligned.m16n8k16.row.col.f32.f16.f16.f32 "
        "{%0,%1,%2,%3}, {%4,%5,%6,%7}, {%8,%9}, {%0,%1,%2,%3};"
        : "+f"(c[0]), "+f"(c[1]), "+f"(c[2]), "+f"(c[3])
        : "r"(a[0]), "r"(a[1]), "r"(a[2]), "r"(a[3]), "r"(b[0]), "r"(b[1]));
}
__device__ __forceinline__ float sigm(float x) { return 1.0f / (1.0f + __expf(-x)); }
__device__ __forceinline__ float tanh_fast(float x) {
    float t = __expf(-2.0f * fabsf(x));
    float r = (1.0f - t) / (1.0f + t);
    return copysignf(r, x);
}

// ---------------- prep: build permuted fp16 B ----------------
// Permuted column C <- (unit u, gate g):
//   C = (u>>4)*64 + (g>>1)*32 + (u&3)*8 + ((u>>2)&3)*2 + (g&1)
// Inverse: u = (C>>6)*16 + ((C>>1)&3)*4 + ((C>>3)&3) ; g = ((C>>5)&1)*2 + (C&1)
__global__ void prep_kernel(const float* __restrict__ R, const float* __restrict__ Kw,
                            const float* __restrict__ bias) {
    int idx = blockIdx.x * blockDim.x + threadIdx.x;   // np*1024 + k
    if (idx >= 4096 * 1024) return;
    int np = idx >> 10;
    int k  = idx & 1023;
    int u = ((np >> 6) << 4) | (((np >> 1) & 3) << 2) | ((np >> 3) & 3);
    int g = (((np >> 5) & 1) << 1) | (np & 1);
    int n = g * 1024 + u;
    float v = R[k * 4096 + n];
    g_B[np * 1024 + k] = __float2half_rn(v);
    if (k == 0) { g_kwP[np] = Kw[n]; g_biasP[np] = bias[n]; }
}

__global__ void zero_kernel() {
    int i = blockIdx.x * blockDim.x + threadIdx.x;
    if (i < BATCH * UNITS) {
        g_c[i] = 0.0f;
        if (i < BATCH * 512) ((uint32_t*)g_A[0])[i] = 0;   // 2M halfs
    }
}

// ---------------- fused LSTM step (GEMM + gates + pred head) ----------------
__global__ void __launch_bounds__(NTHREADS, 2) lstm_mma(
    const float* __restrict__ inputs, const float* __restrict__ w1,
    const float* __restrict__ b1p, const float* __restrict__ w2p,
    const float* __restrict__ b2p, float* __restrict__ out, int s)
{
    extern __shared__ char smem[];
    const uint32_t sb = smem_u32(smem);
    float* predv = reinterpret_cast<float*>(smem + SMEM_GEMM);   // [128]
    float* pp    = predv + 128;                                  // [256]

    const int tid  = threadIdx.x;
    const int wid  = tid >> 5;
    const int lane = tid & 31;
    const int wm   = wid >> 1;       // 0..3 (32-row group)
    const int wn   = wid & 1;        // 0..1 (64-col group)
    const int krot = wid & 3;
    const int mt   = blockIdx.x;
    const int nt   = blockIdx.y;
    const int m0   = mt * BM;
    const int n0p  = nt * BN;
    const int pin  = s & 1;

    const __half* __restrict__ Ain = g_A[pin];
    __half* __restrict__ Aout = g_A[pin ^ 1];

    // -------- prepass: finalize this step's autoregressive input --------
    if (tid < 128) {
        pp[tid * 2] = 0.0f; pp[tid * 2 + 1] = 0.0f;
        if (s >= SEQ_LEN) {
            const float* pr = &g_predpart[(s - 1) & 1][(m0 + tid) * 32];
            float sum = 0.0f;
            #pragma unroll
            for (int j4 = 0; j4 < 8; j4++) {
                float4 v = *reinterpret_cast<const float4*>(&pr[j4 * 4]);
                sum += (v.x + v.y) + (v.z + v.w);
            }
            float x = fmaxf(sum + b1p[0], 0.0f);
            float p = (s == SEQ_LEN) ? x : fmaf(x, w2p[0], b2p[0]);
            predv[tid] = p;
            if (nt == 0) out[(m0 + tid) * OUT_STEPS + (s - SEQ_LEN)] = p;
        }
    }
    // (ordered before epilogue reads by the per-stage barriers below)

    float acc[2][8][4];
    #pragma unroll
    for (int a = 0; a < 2; a++)
        #pragma unroll
        for (int b = 0; b < 8; b++)
            #pragma unroll
            for (int c = 0; c < 4; c++) acc[a][b][c] = 0.0f;

    const int cprow = tid >> 3;     // 0..31
    const int cpch  = tid & 7;

    auto issue = [&](int st) {
        const int buf = st % NBUF;
        const int kk0 = st * BK;
        const uint32_t ab = sb + buf * STG_BYTES;
        const uint32_t bb = ab + A_STG;
        #pragma unroll
        for (int p = 0; p < 4; p++) {                 // A: 128 rows of k64
            int row = cprow + p * 32;
            uint32_t so = row * 128 + ((cpch ^ (row & 7)) << 4);
            cp16(ab + so, &Ain[(m0 + row) * 1024 + kk0 + cpch * 8]);
        }
        #pragma unroll
        for (int p = 0; p < 4; p++) {                 // B: 128 rows
            int row = cprow + p * 32;
            uint32_t so = row * 128 + ((cpch ^ (row & 7)) << 4);
            cp16(bb + so, &g_B[(uint64_t)(n0p + row) * 1024 + kk0 + cpch * 8]);
        }
        cp_commit();
    };

    // fragment lane mapping
    const int a_r  = lane & 15;
    const int a_cb = lane >> 4;
    const int b_rr = (lane & 7) + ((lane >> 4) << 3);
    const int b_cb = (lane >> 3) & 1;

    issue(0);
    issue(1);

    #pragma unroll 1
    for (int st = 0; st < NSTG; st++) {
        if (st == NSTG - 1) cp_wait<0>();
        else                cp_wait<1>();   // stage st landed
        __syncthreads();                    // data visible + slot (st-1)%NBUF free
        if (st + 2 < NSTG) issue(st + 2);   // prefetch 2 ahead into freed slot

        const uint32_t ab = sb + (st % NBUF) * STG_BYTES;
        const uint32_t bb = ab + A_STG;

        #pragma unroll
        for (int kk = 0; kk < 4; kk++) {
            const int kq = (kk + krot) & 3;   // per-warp phase rotation
            uint32_t af[2][4], bf[4][4];
            {
                int ch = kq * 2 + a_cb;
                #pragma unroll
                for (int mi = 0; mi < 2; mi++) {
                    int row = wm * 32 + mi * 16 + a_r;
                    ldsm4(af[mi], ab + row * 128 + ((ch ^ (row & 7)) << 4));
                }
            }
            {
                int ch = kq * 2 + b_cb;
                #pragma unroll
                for (int jp = 0; jp < 4; jp++) {
                    int row = wn * 64 + jp * 16 + b_rr;
                    ldsm4(bf[jp], bb + row * 128 + ((ch ^ (row & 7)) << 4));
                }
            }
            #pragma unroll
            for (int mi = 0; mi < 2; mi++)
                #pragma unroll
                for (int j = 0; j < 8; j++)
                    mma16816(acc[mi][j], af[mi], &bf[j >> 1][(j & 1) * 2]);
        }
    }

    // ---------------- epilogue ----------------
    const int q  = lane & 3;
    const int tr = lane >> 2;
    float kwv[8][2], bsv[8][2];
    #pragma unroll
    for (int j = 0; j < 8; j++) {
        int C = n0p + wn * 64 + 8 * j + 2 * q;
        float2 kw2 = *reinterpret_cast<const float2*>(&g_kwP[C]);
        float2 bs2 = *reinterpret_cast<const float2*>(&g_biasP[C]);
        kwv[j][0] = kw2.x; kwv[j][1] = kw2.y;
        bsv[j][0] = bs2.x; bsv[j][1] = bs2.y;
    }
    const int u0 = (nt * 2 + wn) * 16 + 4 * q;   // 4 consecutive units
    const float4 w1v = *reinterpret_cast<const float4*>(&w1[u0]);

    #pragma unroll
    for (int mi = 0; mi < 2; mi++) {
        #pragma unroll
        for (int h = 0; h < 2; h++) {
            const int rl  = wm * 32 + mi * 16 + tr + 8 * h;   // local row
            const int row = m0 + rl;
            float xb = (s < SEQ_LEN) ? inputs[row * SEQ_LEN + s] : predv[rl];
            float4 cold = *reinterpret_cast<const float4*>(&g_c[row * 1024 + u0]);
            float co[4] = {cold.x, cold.y, cold.z, cold.w};
            float cn[4], hf[4];
            __half hh4[4];
            #pragma unroll
            for (int jl = 0; jl < 4; jl++) {
                float zi = acc[mi][jl    ][2 * h    ] + xb * kwv[jl    ][0] + bsv[jl    ][0];
                float zf = acc[mi][jl    ][2 * h + 1] + xb * kwv[jl    ][1] + bsv[jl    ][1];
                float zg = acc[mi][jl + 4][2 * h    ] + xb * kwv[jl + 4][0] + bsv[jl + 4][0];
                float zo = acc[mi][jl + 4][2 * h + 1] + xb * kwv[jl + 4][1] + bsv[jl + 4][1];
                float ig = sigm(zi);
                float fg = sigm(zf);
                float gg = tanh_fast(zg);
                float og = sigm(zo);
                float cc = fg * co[jl] + ig * gg;
                cn[jl] = cc;
                float hh = og * tanh_fast(cc);
                hf[jl] = hh;
                hh4[jl] = __float2half_rn(hh);
            }
            float4 cv = {cn[0], cn[1], cn[2], cn[3]};
            *reinterpret_cast<float4*>(&g_c[row * 1024 + u0]) = cv;
            uint2 hv;
            memcpy(&hv, hh4, 8);
            *reinterpret_cast<uint2*>(&Aout[row * 1024 + u0]) = hv;
            // pred partial: deterministic quad reduce (q lanes share a row)
            float part = hf[0] * w1v.x + hf[1] * w1v.y + hf[2] * w1v.z + hf[3] * w1v.w;
            part += __shfl_xor_sync(0xffffffffu, part, 1);
            part += __shfl_xor_sync(0xffffffffu, part, 2);
            if (q == 0) pp[rl * 2 + wn] = part;
        }
    }

    __syncthreads();   // pp visible
    if (tid < 128)
        g_predpart[s & 1][(m0 + tid) * 32 + nt] = pp[tid * 2] + pp[tid * 2 + 1];
}

// ---------------- final prediction column out[199] ----------------
__global__ void __launch_bounds__(128) pred_final(
    const float* __restrict__ b1p, const float* __restrict__ w2p,
    const float* __restrict__ b2p, float* __restrict__ out)
{
    const int row = blockIdx.x * 128 + threadIdx.x;
    const float* pr = &g_predpart[(TOTAL_STEPS - 1) & 1][row * 32];
    float sum = 0.0f;
    #pragma unroll
    for (int j4 = 0; j4 < 8; j4++) {
        float4 v = *reinterpret_cast<const float4*>(&pr[j4 * 4]);
        sum += (v.x + v.y) + (v.z + v.w);
    }
    float x = fmaxf(sum + b1p[0], 0.0f);
    out[row * OUT_STEPS + 199] = fmaf(x, w2p[0], b2p[0]);
}

extern "C" void kernel_launch(void* const* d_in, const int* in_sizes, int n_in,
                              void* d_out, int out_size)
{
    const float* inputs = (const float*)d_in[0];
    const float* Kw     = (const float*)d_in[1];
    const float* R      = (const float*)d_in[2];
    const float* bias   = (const float*)d_in[3];
    const float* w1     = (const float*)d_in[4];
    const float* b1     = (const float*)d_in[5];
    const float* w2     = (const float*)d_in[6];
    const float* b2     = (const float*)d_in[7];
    float* out = (float*)d_out;

    cudaFuncSetAttribute(lstm_mma, cudaFuncAttributeMaxDynamicSharedMemorySize, SMEM_TOTAL);

    zero_kernel<<<(BATCH * UNITS + 255) / 256, 256>>>();
    prep_kernel<<<(4096 * 1024 + 255) / 256, 256>>>(R, Kw, bias);

    dim3 grid(BATCH / BM, 4096 / BN);   // (32, 32)

    for (int s = 0; s < TOTAL_STEPS; s++)
        lstm_mma<<<grid, NTHREADS, SMEM_TOTAL>>>(inputs, w1, b1, w2, b2, out, s);

    pred_final<<<BATCH / 128, 128>>>(b1, w2, b2, out);
}

// round 15
// speedup vs baseline: 1.1295x; 1.0025x over previous
#include <cuda_runtime.h>
#include <cuda_fp16.h>
#include <math.h>
#include <cstdint>

#define BATCH 4096
#define UNITS 1024
#define OUT_STEPS 200
#define SEQ_LEN 5
#define TOTAL_STEPS 204

#define BK 64
#define NSTG 16          // K=1024, plain fp16 R
#define BM 128
#define BN 128           // permuted z columns (= 32 units x 4 gates)
#define NTHREADS 256

#define A_STG 16384                     // 128 rows x 128B (k64 fp16)
#define STG_BYTES (2 * 16384)           // A + B = 32KB
#define NBUF 3
#define SMEM_GEMM (NBUF * STG_BYTES)    // 96KB
#define SMEM_TOTAL (SMEM_GEMM + 128 * 4 + 256 * 4)   // + predv[128] + pp[256]

// ---------------- device globals ----------------
__device__ __half g_A[2][BATCH * 1024];   // ping-pong hidden state, fp16
__device__ __half g_B[4096 * 1024];       // permuted R (fp16), row C, K-major
__device__ float g_c[BATCH * UNITS];
__device__ float g_predpart[2][BATCH * 32];  // per-(row,nt) partial h.w1, parity by step
__device__ float g_kwP[4096];
__device__ float g_biasP[4096];

// ---------------- helpers ----------------
__device__ __forceinline__ uint32_t smem_u32(const void* p) {
    uint32_t a;
    asm("{ .reg .u64 t; cvta.to.shared.u64 t, %1; cvt.u32.u64 %0, t; }" : "=r"(a) : "l"(p));
    return a;
}
__device__ __forceinline__ void cp16(uint32_t saddr, const void* gaddr) {
    asm volatile("cp.async.cg.shared.global [%0], [%1], 16;" :: "r"(saddr), "l"(gaddr));
}
__device__ __forceinline__ void cp_commit() {
    asm volatile("cp.async.commit_group;" ::: "memory");
}
template<int N> __device__ __forceinline__ void cp_wait() {
    asm volatile("cp.async.wait_group %0;" :: "n"(N) : "memory");
}
__device__ __forceinline__ void ldsm4(uint32_t* r, uint32_t addr) {
    asm volatile("ldmatrix.sync.aligned.m8n8.x4.shared.b16 {%0,%1,%2,%3}, [%4];"
                 : "=r"(r[0]), "=r"(r[1]), "=r"(r[2]), "=r"(r[3]) : "r"(addr));
}
__device__ __forceinline__ void mma16816(float* c, const uint32_t* a, const uint32_t* b) {
    asm volatile(
        "mma.sync.aligned.m16n8k16.row.col.f32.f16.f16.f32 "
        "{%0,%1,%2,%3}, {%4,%5,%6,%7}, {%8,%9}, {%0,%1,%2,%3};"
        : "+f"(c[0]), "+f"(c[1]), "+f"(c[2]), "+f"(c[3])
        : "r"(a[0]), "r"(a[1]), "r"(a[2]), "r"(a[3]), "r"(b[0]), "r"(b[1]));
}
__device__ __forceinline__ float sigm(float x) { return 1.0f / (1.0f + __expf(-x)); }
__device__ __forceinline__ float tanh_fast(float x) {
    float t = __expf(-2.0f * fabsf(x));
    float r = (1.0f - t) / (1.0f + t);
    return copysignf(r, x);
}

// ---------------- prep: build permuted fp16 B ----------------
// Permuted column C <- (unit u, gate g):
//   C = (u>>4)*64 + (g>>1)*32 + (u&3)*8 + ((u>>2)&3)*2 + (g&1)
// Inverse: u = (C>>6)*16 + ((C>>1)&3)*4 + ((C>>3)&3) ; g = ((C>>5)&1)*2 + (C&1)
__global__ void prep_kernel(const float* __restrict__ R, const float* __restrict__ Kw,
                            const float* __restrict__ bias) {
    int idx = blockIdx.x * blockDim.x + threadIdx.x;   // np*1024 + k
    if (idx >= 4096 * 1024) return;
    int np = idx >> 10;
    int k  = idx & 1023;
    int u = ((np >> 6) << 4) | (((np >> 1) & 3) << 2) | ((np >> 3) & 3);
    int g = (((np >> 5) & 1) << 1) | (np & 1);
    int n = g * 1024 + u;
    float v = R[k * 4096 + n];
    g_B[np * 1024 + k] = __float2half_rn(v);
    if (k == 0) { g_kwP[np] = Kw[n]; g_biasP[np] = bias[n]; }
}

__global__ void zero_kernel() {
    int i = blockIdx.x * blockDim.x + threadIdx.x;
    if (i < BATCH * UNITS) {
        g_c[i] = 0.0f;
        if (i < BATCH * 512) ((uint32_t*)g_A[0])[i] = 0;   // 2M halfs
    }
}

// ---------------- fused LSTM step (GEMM + gates + pred head) ----------------
__global__ void __launch_bounds__(NTHREADS, 2) lstm_mma(
    const float* __restrict__ inputs, const float* __restrict__ w1,
    const float* __restrict__ b1p, const float* __restrict__ w2p,
    const float* __restrict__ b2p, float* __restrict__ out, int s)
{
    extern __shared__ char smem[];
    const uint32_t sb = smem_u32(smem);
    float* predv = reinterpret_cast<float*>(smem + SMEM_GEMM);   // [128]
    float* pp    = predv + 128;                                  // [256]

    const int tid  = threadIdx.x;
    const int wid  = tid >> 5;
    const int lane = tid & 31;
    const int wm   = wid >> 1;       // 0..3 (32-row group)
    const int wn   = wid & 1;        // 0..1 (64-col group)
    const int krot = wid & 3;
    const int mt   = blockIdx.x;
    const int nt   = blockIdx.y;
    const int m0   = mt * BM;
    const int n0p  = nt * BN;
    const int pin  = s & 1;

    const __half* __restrict__ Ain = g_A[pin];
    __half* __restrict__ Aout = g_A[pin ^ 1];

    const int cprow = tid >> 3;     // 0..31
    const int cpch  = tid & 7;

    auto issue = [&](int st) {
        const int buf = st % NBUF;
        const int kk0 = st * BK;
        const uint32_t ab = sb + buf * STG_BYTES;
        const uint32_t bb = ab + A_STG;
        #pragma unroll
        for (int p = 0; p < 4; p++) {                 // A: 128 rows of k64
            int row = cprow + p * 32;
            uint32_t so = row * 128 + ((cpch ^ (row & 7)) << 4);
            cp16(ab + so, &Ain[(m0 + row) * 1024 + kk0 + cpch * 8]);
        }
        #pragma unroll
        for (int p = 0; p < 4; p++) {                 // B: 128 rows
            int row = cprow + p * 32;
            uint32_t so = row * 128 + ((cpch ^ (row & 7)) << 4);
            cp16(bb + so, &g_B[(uint64_t)(n0p + row) * 1024 + kk0 + cpch * 8]);
        }
        cp_commit();
    };

    // start the async pipeline FIRST; prepass LDGs overlap the fill
    issue(0);
    issue(1);

    // -------- prepass: finalize this step's autoregressive input --------
    if (s >= SEQ_LEN && tid < 128) {
        const float* pr = &g_predpart[(s - 1) & 1][(m0 + tid) * 32];
        float sum = 0.0f;
        #pragma unroll
        for (int j4 = 0; j4 < 8; j4++) {
            float4 v = *reinterpret_cast<const float4*>(&pr[j4 * 4]);
            sum += (v.x + v.y) + (v.z + v.w);
        }
        float x = fmaxf(sum + b1p[0], 0.0f);
        float p = (s == SEQ_LEN) ? x : fmaf(x, w2p[0], b2p[0]);
        predv[tid] = p;
        if (nt == 0) out[(m0 + tid) * OUT_STEPS + (s - SEQ_LEN)] = p;
    }
    // (predv ordered before epilogue reads by the per-stage barriers below)

    float acc[2][8][4];
    #pragma unroll
    for (int a = 0; a < 2; a++)
        #pragma unroll
        for (int b = 0; b < 8; b++)
            #pragma unroll
            for (int c = 0; c < 4; c++) acc[a][b][c] = 0.0f;

    // fragment lane mapping
    const int a_r  = lane & 15;
    const int a_cb = lane >> 4;
    const int b_rr = (lane & 7) + ((lane >> 4) << 3);
    const int b_cb = (lane >> 3) & 1;

    #pragma unroll 1
    for (int st = 0; st < NSTG; st++) {
        if (st == NSTG - 1) cp_wait<0>();
        else                cp_wait<1>();   // stage st landed
        __syncthreads();                    // data visible + slot (st-1)%NBUF free
        if (st + 2 < NSTG) issue(st + 2);   // prefetch 2 ahead into freed slot

        const uint32_t ab = sb + (st % NBUF) * STG_BYTES;
        const uint32_t bb = ab + A_STG;

        #pragma unroll
        for (int kk = 0; kk < 4; kk++) {
            const int kq = (kk + krot) & 3;   // per-warp phase rotation
            uint32_t af[2][4], bf[4][4];
            {
                int ch = kq * 2 + a_cb;
                #pragma unroll
                for (int mi = 0; mi < 2; mi++) {
                    int row = wm * 32 + mi * 16 + a_r;
                    ldsm4(af[mi], ab + row * 128 + ((ch ^ (row & 7)) << 4));
                }
            }
            {
                int ch = kq * 2 + b_cb;
                #pragma unroll
                for (int jp = 0; jp < 4; jp++) {
                    int row = wn * 64 + jp * 16 + b_rr;
                    ldsm4(bf[jp], bb + row * 128 + ((ch ^ (row & 7)) << 4));
                }
            }
            #pragma unroll
            for (int mi = 0; mi < 2; mi++)
                #pragma unroll
                for (int j = 0; j < 8; j++)
                    mma16816(acc[mi][j], af[mi], &bf[j >> 1][(j & 1) * 2]);
        }
    }

    // ---------------- epilogue ----------------
    const int q  = lane & 3;
    const int tr = lane >> 2;
    float kwv[8][2], bsv[8][2];
    #pragma unroll
    for (int j = 0; j < 8; j++) {
        int C = n0p + wn * 64 + 8 * j + 2 * q;
        float2 kw2 = *reinterpret_cast<const float2*>(&g_kwP[C]);
        float2 bs2 = *reinterpret_cast<const float2*>(&g_biasP[C]);
        kwv[j][0] = kw2.x; kwv[j][1] = kw2.y;
        bsv[j][0] = bs2.x; bsv[j][1] = bs2.y;
    }
    const int u0 = (nt * 2 + wn) * 16 + 4 * q;   // 4 consecutive units
    const float4 w1v = *reinterpret_cast<const float4*>(&w1[u0]);

    #pragma unroll
    for (int mi = 0; mi < 2; mi++) {
        #pragma unroll
        for (int h = 0; h < 2; h++) {
            const int rl  = wm * 32 + mi * 16 + tr + 8 * h;   // local row
            const int row = m0 + rl;
            float xb = (s < SEQ_LEN) ? inputs[row * SEQ_LEN + s] : predv[rl];
            float4 cold = *reinterpret_cast<const float4*>(&g_c[row * 1024 + u0]);
            float co[4] = {cold.x, cold.y, cold.z, cold.w};
            float cn[4], hf[4];
            __half hh4[4];
            #pragma unroll
            for (int jl = 0; jl < 4; jl++) {
                float zi = acc[mi][jl    ][2 * h    ] + xb * kwv[jl    ][0] + bsv[jl    ][0];
                float zf = acc[mi][jl    ][2 * h + 1] + xb * kwv[jl    ][1] + bsv[jl    ][1];
                float zg = acc[mi][jl + 4][2 * h    ] + xb * kwv[jl + 4][0] + bsv[jl + 4][0];
                float zo = acc[mi][jl + 4][2 * h + 1] + xb * kwv[jl + 4][1] + bsv[jl + 4][1];
                float ig = sigm(zi);
                float fg = sigm(zf);
                float gg = tanh_fast(zg);
                float og = sigm(zo);
                float cc = fg * co[jl] + ig * gg;
                cn[jl] = cc;
                float hh = og * tanh_fast(cc);
                hf[jl] = hh;
                hh4[jl] = __float2half_rn(hh);
            }
            float4 cv = {cn[0], cn[1], cn[2], cn[3]};
            *reinterpret_cast<float4*>(&g_c[row * 1024 + u0]) = cv;
            uint2 hv;
            memcpy(&hv, hh4, 8);
            *reinterpret_cast<uint2*>(&Aout[row * 1024 + u0]) = hv;
            // pred partial: deterministic quad reduce (q lanes share a row)
            float part = hf[0] * w1v.x + hf[1] * w1v.y + hf[2] * w1v.z + hf[3] * w1v.w;
            part += __shfl_xor_sync(0xffffffffu, part, 1);
            part += __shfl_xor_sync(0xffffffffu, part, 2);
            if (q == 0) pp[rl * 2 + wn] = part;
        }
    }

    __syncthreads();   // pp visible (all 256 slots written unconditionally)
    if (tid < 128)
        g_predpart[s & 1][(m0 + tid) * 32 + nt] = pp[tid * 2] + pp[tid * 2 + 1];
}

// ---------------- final prediction column out[199] ----------------
__global__ void __launch_bounds__(128) pred_final(
    const float* __restrict__ b1p, const float* __restrict__ w2p,
    const float* __restrict__ b2p, float* __restrict__ out)
{
    const int row = blockIdx.x * 128 + threadIdx.x;
    const float* pr = &g_predpart[(TOTAL_STEPS - 1) & 1][row * 32];
    float sum = 0.0f;
    #pragma unroll
    for (int j4 = 0; j4 < 8; j4++) {
        float4 v = *reinterpret_cast<const float4*>(&pr[j4 * 4]);
        sum += (v.x + v.y) + (v.z + v.w);
    }
    float x = fmaxf(sum + b1p[0], 0.0f);
    out[row * OUT_STEPS + 199] = fmaf(x, w2p[0], b2p[0]);
}

extern "C" void kernel_launch(void* const* d_in, const int* in_sizes, int n_in,
                              void* d_out, int out_size)
{
    const float* inputs = (const float*)d_in[0];
    const float* Kw     = (const float*)d_in[1];
    const float* R      = (const float*)d_in[2];
    const float* bias   = (const float*)d_in[3];
    const float* w1     = (const float*)d_in[4];
    const float* b1     = (const float*)d_in[5];
    const float* w2     = (const float*)d_in[6];
    const float* b2     = (const float*)d_in[7];
    float* out = (float*)d_out;

    cudaFuncSetAttribute(lstm_mma, cudaFuncAttributeMaxDynamicSharedMemorySize, SMEM_TOTAL);

    zero_kernel<<<(BATCH * UNITS + 255) / 256, 256>>>();
    prep_kernel<<<(4096 * 1024 + 255) / 256, 256>>>(R, Kw, bias);

    dim3 grid(BATCH / BM, 4096 / BN);   // (32, 32)

    for (int s = 0; s < TOTAL_STEPS; s++)
        lstm_mma<<<grid, NTHREADS, SMEM_TOTAL>>>(inputs, w1, b1, w2, b2, out, s);

    pred_final<<<BATCH / 128, 128>>>(b1, w2, b2, out);
}

// round 17
// speedup vs baseline: 1.1516x; 1.0195x over previous
#include <cuda_runtime.h>
#include <cuda_fp16.h>
#include <math.h>
#include <cstdint>

#define BATCH 4096
#define UNITS 1024
#define OUT_STEPS 200
#define SEQ_LEN 5

#define BK 64
#define NSTG 16          // K=1024, plain fp16 R
#define BM 128
#define BN 128           // permuted z columns (= 32 units x 4 gates)
#define NTHREADS 256

#define A_STG 16384                     // 128 rows x 128B (k64 fp16)
#define STG_BYTES (2 * 16384)           // A + B = 32KB
#define NBUF 3
#define SMEM_TOTAL (NBUF * STG_BYTES)   // 96KB -> 2 CTAs/SM

// ---------------- device globals ----------------
__device__ __half g_A[2][BATCH * 1024];   // ping-pong hidden state, fp16
__device__ __half g_B[4096 * 1024];       // permuted R (fp16), row C, K-major
__device__ float g_c[BATCH * UNITS];
__device__ float g_pred[BATCH];
__device__ float g_kwP[4096];
__device__ float g_biasP[4096];

// ---------------- helpers ----------------
__device__ __forceinline__ uint32_t smem_u32(const void* p) {
    uint32_t a;
    asm("{ .reg .u64 t; cvta.to.shared.u64 t, %1; cvt.u32.u64 %0, t; }" : "=r"(a) : "l"(p));
    return a;
}
__device__ __forceinline__ void cp16(uint32_t saddr, const void* gaddr) {
    asm volatile("cp.async.cg.shared.global [%0], [%1], 16;" :: "r"(saddr), "l"(gaddr));
}
__device__ __forceinline__ void cp_commit() {
    asm volatile("cp.async.commit_group;" ::: "memory");
}
template<int N> __device__ __forceinline__ void cp_wait() {
    asm volatile("cp.async.wait_group %0;" :: "n"(N) : "memory");
}
__device__ __forceinline__ void ldsm4(uint32_t* r, uint32_t addr) {
    asm volatile("ldmatrix.sync.aligned.m8n8.x4.shared.b16 {%0,%1,%2,%3}, [%4];"
                 : "=r"(r[0]), "=r"(r[1]), "=r"(r[2]), "=r"(r[3]) : "r"(addr));
}
__device__ __forceinline__ void mma16816(float* c, const uint32_t* a, const uint32_t* b) {
    asm volatile(
        "mma.sync.aligned.m16n8k16.row.col.f32.f16.f16.f32 "
        "{%0,%1,%2,%3}, {%4,%5,%6,%7}, {%8,%9}, {%0,%1,%2,%3};"
        : "+f"(c[0]), "+f"(c[1]), "+f"(c[2]), "+f"(c[3])
        : "r"(a[0]), "r"(a[1]), "r"(a[2]), "r"(a[3]), "r"(b[0]), "r"(b[1]));
}
__device__ __forceinline__ float sigm(float x) { return 1.0f / (1.0f + __expf(-x)); }
__device__ __forceinline__ float tanh_fast(float x) {
    float t = __expf(-2.0f * fabsf(x));
    float r = (1.0f - t) / (1.0f + t);
    return copysignf(r, x);
}

// ---------------- prep: build permuted fp16 B ----------------
// Permuted column C <- (unit u, gate g):
//   C = (u>>4)*64 + (g>>1)*32 + (u&3)*8 + ((u>>2)&3)*2 + (g&1)
// Inverse: u = (C>>6)*16 + ((C>>1)&3)*4 + ((C>>3)&3) ; g = ((C>>5)&1)*2 + (C&1)
__global__ void prep_kernel(const float* __restrict__ R, const float* __restrict__ Kw,
                            const float* __restrict__ bias) {
    int idx = blockIdx.x * blockDim.x + threadIdx.x;   // np*1024 + k
    if (idx >= 4096 * 1024) return;
    int np = idx >> 10;
    int k  = idx & 1023;
    int u = ((np >> 6) << 4) | (((np >> 1) & 3) << 2) | ((np >> 3) & 3);
    int g = (((np >> 5) & 1) << 1) | (np & 1);
    int n = g * 1024 + u;
    float v = R[k * 4096 + n];
    g_B[np * 1024 + k] = __float2half_rn(v);
    if (k == 0) { g_kwP[np] = Kw[n]; g_biasP[np] = bias[n]; }
}

__global__ void zero_kernel() {
    int i = blockIdx.x * blockDim.x + threadIdx.x;
    if (i < BATCH * UNITS) {
        g_c[i] = 0.0f;
        if (i < BATCH * 512) ((uint32_t*)g_A[0])[i] = 0;   // 2M halfs
    }
}

// ---------------- fused LSTM step (fp16 mma.sync GEMM + gates) ----------------
__global__ void __launch_bounds__(NTHREADS, 2) lstm_mma(const float* __restrict__ xsrc,
                                                        int xstride, int pin) {
    extern __shared__ char smem[];
    const uint32_t sb = smem_u32(smem);
    const int tid  = threadIdx.x;
    const int wid  = tid >> 5;
    const int lane = tid & 31;
    const int wm   = wid >> 1;       // 0..3 (32-row group)
    const int wn   = wid & 1;        // 0..1 (64-col group)
    const int krot = wid & 3;        // kk-phase rotation per warp
    const int m0   = blockIdx.x * BM;
    const int nt   = blockIdx.y;
    const int n0p  = nt * BN;        // permuted-col base

    const __half* __restrict__ Ain = g_A[pin];
    __half* __restrict__ Aout = g_A[pin ^ 1];

    float acc[2][8][4];
    #pragma unroll
    for (int a = 0; a < 2; a++)
        #pragma unroll
        for (int b = 0; b < 8; b++)
            #pragma unroll
            for (int c = 0; c < 4; c++) acc[a][b][c] = 0.0f;

    const int cprow = tid >> 3;     // 0..31
    const int cpch  = tid & 7;

    auto issue = [&](int s) {
        const int buf = s % NBUF;
        const int kk0 = s * BK;
        const uint32_t ab = sb + buf * STG_BYTES;
        const uint32_t bb = ab + A_STG;
        #pragma unroll
        for (int p = 0; p < 4; p++) {                 // A: 128 rows of k64
            int row = cprow + p * 32;
            uint32_t so = row * 128 + ((cpch ^ (row & 7)) << 4);
            cp16(ab + so, &Ain[(m0 + row) * 1024 + kk0 + cpch * 8]);
        }
        #pragma unroll
        for (int p = 0; p < 4; p++) {                 // B: 128 rows
            int row = cprow + p * 32;
            uint32_t so = row * 128 + ((cpch ^ (row & 7)) << 4);
            cp16(bb + so, &g_B[(uint64_t)(n0p + row) * 1024 + kk0 + cpch * 8]);
        }
        cp_commit();
    };

    // fragment lane mapping
    const int a_r  = lane & 15;
    const int a_cb = lane >> 4;
    const int b_rr = (lane & 7) + ((lane >> 4) << 3);
    const int b_cb = (lane >> 3) & 1;

    // NOTE (PDL): when launched programmatically after pred_kernel, the
    // previous lstm step is already fully complete (pred launched normally
    // after it), so Ain and g_B reads here are safe BEFORE the dependency
    // sync. Only g_pred (written by the concurrent pred) needs the sync,
    // which happens below, right before the epilogue.
    issue(0);
    issue(1);

    #pragma unroll 1
    for (int s = 0; s < NSTG; s++) {
        if (s == NSTG - 1) cp_wait<0>();
        else               cp_wait<1>();   // stage s landed
        __syncthreads();                   // data visible + slot (s-1)%NBUF free
        if (s + 2 < NSTG) issue(s + 2);    // prefetch 2 ahead into freed slot

        const uint32_t ab = sb + (s % NBUF) * STG_BYTES;
        const uint32_t bb = ab + A_STG;

        #pragma unroll
        for (int kk = 0; kk < 4; kk++) {
            const int kq = (kk + krot) & 3;   // per-warp phase rotation
            uint32_t af[2][4], bf[4][4];
            {
                int ch = kq * 2 + a_cb;
                #pragma unroll
                for (int mi = 0; mi < 2; mi++) {
                    int row = wm * 32 + mi * 16 + a_r;
                    ldsm4(af[mi], ab + row * 128 + ((ch ^ (row & 7)) << 4));
                }
            }
            {
                int ch = kq * 2 + b_cb;
                #pragma unroll
                for (int jp = 0; jp < 4; jp++) {
                    int row = wn * 64 + jp * 16 + b_rr;
                    ldsm4(bf[jp], bb + row * 128 + ((ch ^ (row & 7)) << 4));
                }
            }
            #pragma unroll
            for (int mi = 0; mi < 2; mi++)
                #pragma unroll
                for (int j = 0; j < 8; j++)
                    mma16816(acc[mi][j], af[mi], &bf[j >> 1][(j & 1) * 2]);
        }
    }

    // Wait for the predecessor kernel (pred writing g_pred) before epilogue.
    cudaGridDependencySynchronize();

    // ---------------- epilogue ----------------
    const int q  = lane & 3;
    const int tr = lane >> 2;
    float kwv[8][2], bsv[8][2];
    #pragma unroll
    for (int j = 0; j < 8; j++) {
        int C = n0p + wn * 64 + 8 * j + 2 * q;
        float2 kw2 = *reinterpret_cast<const float2*>(&g_kwP[C]);
        float2 bs2 = *reinterpret_cast<const float2*>(&g_biasP[C]);
        kwv[j][0] = kw2.x; kwv[j][1] = kw2.y;
        bsv[j][0] = bs2.x; bsv[j][1] = bs2.y;
    }
    const int u0 = (nt * 2 + wn) * 16 + 4 * q;   // 4 consecutive units

    #pragma unroll
    for (int mi = 0; mi < 2; mi++) {
        #pragma unroll
        for (int h = 0; h < 2; h++) {
            int row = m0 + wm * 32 + mi * 16 + tr + 8 * h;
            float xb = xsrc ? xsrc[row * xstride] : g_pred[row];
            float4 cold = *reinterpret_cast<const float4*>(&g_c[row * 1024 + u0]);
            float co[4] = {cold.x, cold.y, cold.z, cold.w};
            float cn[4];
            __half hh4[4];
            #pragma unroll
            for (int jl = 0; jl < 4; jl++) {
                float zi = acc[mi][jl    ][2 * h    ] + xb * kwv[jl    ][0] + bsv[jl    ][0];
                float zf = acc[mi][jl    ][2 * h + 1] + xb * kwv[jl    ][1] + bsv[jl    ][1];
                float zg = acc[mi][jl + 4][2 * h    ] + xb * kwv[jl + 4][0] + bsv[jl + 4][0];
                float zo = acc[mi][jl + 4][2 * h + 1] + xb * kwv[jl + 4][1] + bsv[jl + 4][1];
                float ig = sigm(zi);
                float fg = sigm(zf);
                float gg = tanh_fast(zg);
                float og = sigm(zo);
                float cc = fg * co[jl] + ig * gg;
                cn[jl] = cc;
                float hh = og * tanh_fast(cc);
                hh4[jl] = __float2half_rn(hh);
            }
            float4 cv = {cn[0], cn[1], cn[2], cn[3]};
            *reinterpret_cast<float4*>(&g_c[row * 1024 + u0]) = cv;
            uint2 hv;
            memcpy(&hv, hh4, 8);
            *reinterpret_cast<uint2*>(&Aout[row * 1024 + u0]) = hv;
        }
    }
}

// ---------------- prediction head ----------------
__global__ void __launch_bounds__(256) pred_kernel(
    const float* __restrict__ w1, const float* __restrict__ b1,
    const float* __restrict__ w2, const float* __restrict__ b2,
    float* __restrict__ out, int tcol, int pin, int final_dense)
{
    // Fire the programmatic-launch trigger immediately: the next lstm step's
    // GEMM only needs data that is already final when this kernel starts.
    cudaTriggerProgrammaticLaunchCompletion();

    int warp = (blockIdx.x * blockDim.x + threadIdx.x) >> 5;
    int lane = threadIdx.x & 31;
    if (warp >= BATCH) return;
    const __half* __restrict__ ha = &g_A[pin][warp * 1024];
    float s = 0.0f;
    #pragma unroll 4
    for (int k = lane; k < UNITS; k += 32)
        s = fmaf(__half2float(ha[k]), w1[k], s);
    #pragma unroll
    for (int off = 16; off; off >>= 1) s += __shfl_down_sync(0xffffffffu, s, off);
    if (lane == 0) {
        float x = fmaxf(s + b1[0], 0.0f);
        float p = final_dense ? fmaf(x, w2[0], b2[0]) : x;
        out[warp * OUT_STEPS + tcol] = p;
        g_pred[warp] = p;
    }
}

// ---------------- host ----------------
static void launch_lstm_pdl(dim3 grid, const float* xsrc, int xstride, int pin) {
    cudaLaunchConfig_t cfg = {};
    cfg.gridDim = grid;
    cfg.blockDim = dim3(NTHREADS, 1, 1);
    cfg.dynamicSmemBytes = SMEM_TOTAL;
    cfg.stream = 0;
    cudaLaunchAttribute attr[1];
    attr[0].id = cudaLaunchAttributeProgrammaticStreamSerialization;
    attr[0].val.programmaticStreamSerializationAllowed = 1;
    cfg.attrs = attr;
    cfg.numAttrs = 1;
    cudaLaunchKernelEx(&cfg, lstm_mma, xsrc, xstride, pin);
}

extern "C" void kernel_launch(void* const* d_in, const int* in_sizes, int n_in,
                              void* d_out, int out_size)
{
    const float* inputs = (const float*)d_in[0];
    const float* Kw     = (const float*)d_in[1];
    const float* R      = (const float*)d_in[2];
    const float* bias   = (const float*)d_in[3];
    const float* w1     = (const float*)d_in[4];
    const float* b1     = (const float*)d_in[5];
    const float* w2     = (const float*)d_in[6];
    const float* b2     = (const float*)d_in[7];
    float* out = (float*)d_out;

    cudaFuncSetAttribute(lstm_mma, cudaFuncAttributeMaxDynamicSharedMemorySize, SMEM_TOTAL);

    zero_kernel<<<(BATCH * UNITS + 255) / 256, 256>>>();
    prep_kernel<<<(4096 * 1024 + 255) / 256, 256>>>(R, Kw, bias);

    dim3 grid(BATCH / BM, 4096 / BN);   // (32, 32)
    int pp = 0;

    for (int t = 0; t < SEQ_LEN; t++) {
        launch_lstm_pdl(grid, inputs + t, SEQ_LEN, pp);
        pp ^= 1;
    }
    pred_kernel<<<BATCH / 8, 256>>>(w1, b1, w2, b2, out, 0, pp, 0);

    for (int j = 1; j < OUT_STEPS; j++) {
        launch_lstm_pdl(grid, nullptr, 1, pp);
        pp ^= 1;
        pred_kernel<<<BATCH / 8, 256>>>(w1, b1, w2, b2, out, j, pp, 1);
    }
}